// round 4
// baseline (speedup 1.0000x reference)
#include <cuda_runtime.h>
#include <math_constants.h>

// Problem constants
#define NSL     24
#define BB      16
#define CCH     512
#define HWN     256          // H*W
#define FEAT_IN 1024
#define CLASSES 3
#define CG      8            // c-values per CTA (one per warp)
#define GRID    (BB * (CCH / CG))   // 1024

// Persistent scratch (zero at module load; each launch restores it to zero).
__device__ float        g_acc[BB * CLASSES];
__device__ unsigned int g_count;

// Single fused kernel: grid = 1024 CTAs x 256 threads, one wave.
// Warp w owns channel c = cg*8 + w and streams all 25 segments (feat_f + 24
// oct slices, 1KB each) with 2x float4/lane (__ldcs) + xor-shuffle reduction.
// Head: warp lane0 -> shared acc (3 floats) -> 3 REDG/CTA into g_acc.
// Last CTA (ticket) drains g_acc via atomicExch (read+rezero), adds bias,
// writes out, resets the counter — state is clean for the next graph replay.
__global__ __launch_bounds__(256, 7) void fused_kernel(
    const float* __restrict__ feat_f_map,
    const float* __restrict__ oct_maps,
    const float* __restrict__ head_w,
    const float* __restrict__ head_b,
    float* __restrict__ out)
{
    const int gid  = blockIdx.x;          // 0..1023
    const int b    = gid >> 6;            // / 64
    const int cg   = gid & 63;            // % 64
    const int warp = threadIdx.x >> 5;    // 0..7
    const int lane = threadIdx.x & 31;
    const int c    = cg * CG + warp;      // this warp's channel

    __shared__ float    s_acc[CLASSES];
    __shared__ unsigned s_ticket;
    if (threadIdx.x < CLASSES) s_acc[threadIdx.x] = 0.f;
    __syncthreads();

    // feat_f segment: contiguous 1KB
    float sff;
    {
        const float4* p = (const float4*)(feat_f_map + ((size_t)(b * CCH + c) << 8));
        float4 v0 = __ldcs(p + lane), v1 = __ldcs(p + lane + 32);
        float s = (v0.x + v0.y) + (v0.z + v0.w)
                + (v1.x + v1.y) + (v1.z + v1.w);
        #pragma unroll
        for (int off = 16; off; off >>= 1)
            s += __shfl_xor_sync(0xffffffffu, s, off);
        sff = s;
    }

    // 24 oct slices: max over slice means
    float vmax = -CUDART_INF_F;
    #pragma unroll 3
    for (int s = 0; s < NSL; s++) {
        const float4* p = (const float4*)
            (oct_maps + ((((size_t)s * BB + b) * CCH + c) << 8));
        float4 v0 = __ldcs(p + lane), v1 = __ldcs(p + lane + 32);
        float t = (v0.x + v0.y) + (v0.z + v0.w)
                + (v1.x + v1.y) + (v1.z + v1.w);
        #pragma unroll
        for (int off = 16; off; off >>= 1)
            t += __shfl_xor_sync(0xffffffffu, t, off);
        vmax = fmaxf(vmax, t);
    }

    // Head contribution for this c (lane 0 of each warp)
    if (lane == 0) {
        const float inv = 1.0f / (float)HWN;
        const float ff = sff  * inv;      // feat_f[b][c]
        const float fo = vmax * inv;      // feat_o[b][c] = max_s mean_HW
        #pragma unroll
        for (int cl = 0; cl < CLASSES; cl++) {
            const float* w = head_w + cl * FEAT_IN;
            atomicAdd(&s_acc[cl], ff * w[c] + fo * w[CCH + c]);
        }
    }
    __syncthreads();

    if (threadIdx.x < CLASSES)
        atomicAdd(&g_acc[b * CLASSES + threadIdx.x], s_acc[threadIdx.x]);

    // Completion ticket (release: fence before counter increment)
    __threadfence();
    if (threadIdx.x == 0)
        s_ticket = atomicAdd(&g_count, 1u);
    __syncthreads();

    if (s_ticket == GRID - 1) {
        // Last CTA: finalize output and restore scratch state.
        if (threadIdx.x < BB * CLASSES) {
            float v = atomicExch(&g_acc[threadIdx.x], 0.f);  // read + rezero
            out[threadIdx.x] = v + head_b[threadIdx.x % CLASSES];
        }
        if (threadIdx.x == 0)
            atomicExch(&g_count, 0u);
    }
}

extern "C" void kernel_launch(void* const* d_in, const int* in_sizes, int n_in,
                              void* d_out, int out_size)
{
    const float* feat_f_map = (const float*)d_in[0];  // (16,512,16,16)
    const float* oct_maps   = (const float*)d_in[1];  // (24,16,512,16,16)
    const float* head_w     = (const float*)d_in[2];  // (3,1024)
    const float* head_b     = (const float*)d_in[3];  // (3,)
    float* out = (float*)d_out;                        // (16,3)

    fused_kernel<<<GRID, 256>>>(feat_f_map, oct_maps, head_w, head_b, out);
}

// round 5
// speedup vs baseline: 1.0009x; 1.0009x over previous
#include <cuda_runtime.h>
#include <math_constants.h>

// Problem constants
#define NSL     24
#define BB      16
#define CCH     512
#define HWN     256          // H*W
#define FEAT_IN 1024
#define CLASSES 3
#define CG      8            // c-values per CTA (one per warp)
#define CTAS_PER_B (CCH / CG)       // 64
#define GRID    (BB * CTAS_PER_B)   // 1024

// Persistent scratch (zero at module load; each launch restores it to zero).
__device__ float        g_acc[BB * CLASSES];
__device__ unsigned int g_count[BB];

// Single fused kernel: grid = 1024 CTAs x 256 threads, one wave.
// Warp w owns channel c = cg*8 + w and streams all 25 segments (feat_f + 24
// oct slices, 1KB each) with 2x float4/lane + xor-shuffle reductions.
// Head: warp lane0 -> shared acc (3 floats) -> 3 REDG/CTA into g_acc[b].
// Per-b ticket: the 64th CTA of batch b drains g_acc[b] via atomicExch
// (read + rezero for next graph replay), adds bias, writes out[b].
__global__ __launch_bounds__(256, 7) void fused_kernel(
    const float* __restrict__ feat_f_map,
    const float* __restrict__ oct_maps,
    const float* __restrict__ head_w,
    const float* __restrict__ head_b,
    float* __restrict__ out)
{
    const int gid  = blockIdx.x;          // 0..1023
    const int b    = gid >> 6;            // / 64
    const int cg   = gid & 63;            // % 64
    const int warp = threadIdx.x >> 5;    // 0..7
    const int lane = threadIdx.x & 31;
    const int c    = cg * CG + warp;      // this warp's channel

    __shared__ float    s_acc[CLASSES];
    __shared__ unsigned s_ticket;
    if (threadIdx.x < CLASSES) s_acc[threadIdx.x] = 0.f;
    __syncthreads();

    // feat_f segment: contiguous 1KB
    float sff;
    {
        const float4* p = (const float4*)(feat_f_map + ((size_t)(b * CCH + c) << 8));
        float4 v0 = p[lane], v1 = p[lane + 32];
        float s = (v0.x + v0.y) + (v0.z + v0.w)
                + (v1.x + v1.y) + (v1.z + v1.w);
        #pragma unroll
        for (int off = 16; off; off >>= 1)
            s += __shfl_xor_sync(0xffffffffu, s, off);
        sff = s;
    }

    // 24 oct slices: max over slice means
    float vmax = -CUDART_INF_F;
    #pragma unroll 3
    for (int s = 0; s < NSL; s++) {
        const float4* p = (const float4*)
            (oct_maps + ((((size_t)s * BB + b) * CCH + c) << 8));
        float4 v0 = p[lane], v1 = p[lane + 32];
        float t = (v0.x + v0.y) + (v0.z + v0.w)
                + (v1.x + v1.y) + (v1.z + v1.w);
        #pragma unroll
        for (int off = 16; off; off >>= 1)
            t += __shfl_xor_sync(0xffffffffu, t, off);
        vmax = fmaxf(vmax, t);
    }

    // Head contribution for this c (lane 0 of each warp)
    if (lane == 0) {
        const float inv = 1.0f / (float)HWN;
        const float ff = sff  * inv;      // feat_f[b][c]
        const float fo = vmax * inv;      // feat_o[b][c] = max_s mean_HW
        #pragma unroll
        for (int cl = 0; cl < CLASSES; cl++) {
            const float* w = head_w + cl * FEAT_IN;
            atomicAdd(&s_acc[cl], ff * w[c] + fo * w[CCH + c]);
        }
    }
    __syncthreads();

    if (threadIdx.x < CLASSES)
        atomicAdd(&g_acc[b * CLASSES + threadIdx.x], s_acc[threadIdx.x]);

    // Per-b completion ticket (release: fence before counter increment)
    __threadfence();
    if (threadIdx.x == 0)
        s_ticket = atomicAdd(&g_count[b], 1u);
    __syncthreads();

    if (s_ticket == CTAS_PER_B - 1) {
        // Last CTA of this b: finalize its 3 outputs, restore scratch state.
        if (threadIdx.x < CLASSES) {
            float v = atomicExch(&g_acc[b * CLASSES + threadIdx.x], 0.f);
            out[b * CLASSES + threadIdx.x] = v + head_b[threadIdx.x];
        }
        if (threadIdx.x == 0)
            atomicExch(&g_count[b], 0u);
    }
}

extern "C" void kernel_launch(void* const* d_in, const int* in_sizes, int n_in,
                              void* d_out, int out_size)
{
    const float* feat_f_map = (const float*)d_in[0];  // (16,512,16,16)
    const float* oct_maps   = (const float*)d_in[1];  // (24,16,512,16,16)
    const float* head_w     = (const float*)d_in[2];  // (3,1024)
    const float* head_b     = (const float*)d_in[3];  // (3,)
    float* out = (float*)d_out;                        // (16,3)

    fused_kernel<<<GRID, 256>>>(feat_f_map, oct_maps, head_w, head_b, out);
}